// round 16
// baseline (speedup 1.0000x reference)
#include <cuda_runtime.h>
#include <cuda_fp16.h>
#include <cstdint>

// ============================ problem constants ============================
// B=8, N=300 -> BN=2400; G=4; P=O=32; CG=DG=64; IN_DIM=OUT_DIM=256; TEMPER=8

// ===================== scratch (__device__ globals) ========================
__device__ float g_P[9830400];    // split-K slices of (2400,256)

__device__ __half g_Mh[39321600];                 // hi only (B operand)
__device__ __half g_Vh[39321600];
__device__ __half g_Sh[9830400],  g_Sl[9830400];  // A operand: hi+lo
__device__ __half g_Qh[9830400],  g_Ql[9830400];

__device__ __half g_qvh[614400],  g_qvl[614400];  // A operand: hi+lo
__device__ __half g_mwh[4194304];                 // B operands: hi only
__device__ __half g_vwh[4194304];
__device__ __half g_swh[1048576];
__device__ __half g_qwh[1048576];
__device__ __half g_Wvh[2097152];
__device__ __half g_W2h[2097152];
__device__ __half g_FMSh[19660800], g_FMSl[19660800];  // A operand: hi+lo
__device__ __half g_FCh[19660800],  g_FCl[19660800];

// ============================ small helpers ================================
__device__ __forceinline__ uint32_t smem_u32(const void* p) {
    uint32_t a;
    asm("{ .reg .u64 t; cvta.to.shared.u64 t, %1; cvt.u32.u64 %0, t; }"
        : "=r"(a) : "l"(p));
    return a;
}
__device__ __forceinline__ void split_h(float x, __half& h, __half& l) {
    h = __float2half_rn(x);
    l = __float2half_rn(x - __half2float(h));
}
__device__ __forceinline__ void ldmx4(uint32_t r[4], uint32_t addr) {
    asm volatile("ldmatrix.sync.aligned.m8n8.x4.shared.b16 {%0,%1,%2,%3}, [%4];"
                 : "=r"(r[0]), "=r"(r[1]), "=r"(r[2]), "=r"(r[3]) : "r"(addr));
}
__device__ __forceinline__ void ldmx4_t(uint32_t r[4], uint32_t addr) {
    asm volatile("ldmatrix.sync.aligned.m8n8.x4.trans.shared.b16 {%0,%1,%2,%3}, [%4];"
                 : "=r"(r[0]), "=r"(r[1]), "=r"(r[2]), "=r"(r[3]) : "r"(addr));
}
__device__ __forceinline__ void mma_f16(float d[4], const uint32_t a[4],
                                        const uint32_t b0, const uint32_t b1) {
    asm volatile(
        "mma.sync.aligned.m16n8k16.row.col.f32.f16.f16.f32 "
        "{%0,%1,%2,%3}, {%4,%5,%6,%7}, {%8,%9}, {%0,%1,%2,%3};"
        : "+f"(d[0]), "+f"(d[1]), "+f"(d[2]), "+f"(d[3])
        : "r"(a[0]), "r"(a[1]), "r"(a[2]), "r"(a[3]), "r"(b0), "r"(b1));
}
__device__ __forceinline__ void split2_pack(float a, float b, uint32_t& hp, uint32_t& lp) {
    __half ha = __float2half_rn(a), hb = __float2half_rn(b);
    union { __half h[2]; uint32_t u; } H, L;
    H.h[0] = ha; H.h[1] = hb;
    L.h[0] = __float2half_rn(a - __half2float(ha));
    L.h[1] = __float2half_rn(b - __half2float(hb));
    hp = H.u; lp = L.u;
}
__device__ __forceinline__ uint32_t pack2h(float a, float b) {
    union { __half h[2]; uint32_t u; } U;
    U.h[0] = __float2half_rn(a); U.h[1] = __float2half_rn(b);
    return U.u;
}
// cp.async helpers
__device__ __forceinline__ void cp_async16(uint32_t saddr, const void* g) {
    asm volatile("cp.async.cg.shared.global [%0], [%1], 16;"
                 :: "r"(saddr), "l"(g));
}
__device__ __forceinline__ void cp_async16p(uint32_t saddr, const void* g, bool v) {
    int sz = v ? 16 : 0;
    asm volatile("cp.async.cg.shared.global [%0], [%1], 16, %2;"
                 :: "r"(saddr), "l"(g), "r"(sz));
}
__device__ __forceinline__ void cp_commit() {
    asm volatile("cp.async.commit_group;" ::: "memory");
}
__device__ __forceinline__ void cp_wait0() {
    asm volatile("cp.async.wait_group 0;" ::: "memory");
}
__device__ __forceinline__ void cp_wait1() {
    asm volatile("cp.async.wait_group 1;" ::: "memory");
}

// ================= operand split prep (fp32 -> fp16) =======================
// z==0 (qv): hi+lo. z>=1 (weights, B operands): hi only.
__global__ void __launch_bounds__(256) split_kernel(
    const float* __restrict__ qv, const float* __restrict__ mw,
    const float* __restrict__ vw, const float* __restrict__ sw,
    const float* __restrict__ qw, const float* __restrict__ Wv,
    const float* __restrict__ W2)
{
    const float* src; __half *dh, *dl = nullptr; int n;
    switch (blockIdx.z) {
        case 0: src = qv; dh = g_qvh; dl = g_qvl; n = 614400;  break;
        case 1: src = mw; dh = g_mwh; n = 4194304; break;
        case 2: src = vw; dh = g_vwh; n = 4194304; break;
        case 3: src = sw; dh = g_swh; n = 1048576; break;
        case 4: src = qw; dh = g_qwh; n = 1048576; break;
        case 5: src = Wv; dh = g_Wvh; n = 2097152; break;
        default:src = W2; dh = g_W2h; n = 2097152; break;
    }
    int i = (blockIdx.x * 256 + threadIdx.x) * 4;
    if (i >= n) return;
    float4 v = *(const float4*)(src + i);
    union U { __half b[4]; uint2 u; } H, L;
    split_h(v.x, H.b[0], L.b[0]);
    split_h(v.y, H.b[1], L.b[1]);
    split_h(v.z, H.b[2], L.b[2]);
    split_h(v.w, H.b[3], L.b[3]);
    *(uint2*)(dh + i) = H.u;
    if (dl) *(uint2*)(dl + i) = L.u;
}

// ====== shared GEMM core: fp16, NP passes, cp.async 3-stage pipeline =======
static constexpr int RS = 40;
static constexpr int BUF = 128 * RS * 2;
static constexpr int STAGE_BYTES = 3 * BUF;         // Ah|Al|Bh
static constexpr int GEMM_SMEM = 3 * STAGE_BYTES;   // 92160 B

template<int NP>
__device__ __forceinline__ void gemm_core(
    float acc[2][8][4],
    const __half* __restrict__ Ah, const __half* __restrict__ Al,
    const __half* __restrict__ Wh,
    char* sm, int m0, int n0, int M, int lda, int kBegin, int NC)
{
    const int tid = threadIdx.x, wid = tid >> 5, lane = tid & 31;
    const int wm = (wid & 3) * 32;
    const int wn = (wid >> 2) * 64;
    const int lrow = tid >> 2;
    const int lseg = (tid & 3) * 8;
    const uint32_t smb = smem_u32(sm);

    const int arow = lane & 15, acol = (lane >> 4) * 8;
    const int bgrp = lane >> 3, brow = lane & 7;
    const int bn_off = (bgrp >> 1) * 8 + brow;
    const int bk_off = (bgrp & 1) * 8;

#pragma unroll
    for (int i = 0; i < 2; i++)
#pragma unroll
        for (int j = 0; j < 8; j++)
#pragma unroll
            for (int q = 0; q < 4; q++) acc[i][j][q] = 0.f;

    auto issue = [&](int c, int s) {
        const int kk = kBegin + c * 32;
        const uint32_t sb = smb + s * STAGE_BYTES;
#pragma unroll
        for (int j = 0; j < 2; j++) {
            int row = lrow + 64 * j;
            int gm = m0 + row;
            bool va = (gm < M);
            int gmc = va ? gm : (M - 1);
            uint32_t off = (uint32_t)(row * RS + lseg) * 2;
            cp_async16p(sb + off, Ah + (size_t)gmc * lda + kk + lseg, va);
            if (NP == 2)
                cp_async16p(sb + BUF + off, Al + (size_t)gmc * lda + kk + lseg, va);
            cp_async16(sb + 2 * BUF + off, Wh + (size_t)(n0 + row) * lda + kk + lseg);
        }
    };

    issue(0, 0); cp_commit();
    if (NC > 1) { issue(1, 1); cp_commit(); }

    for (int c = 0; c < NC; c++) {
        if (c + 1 < NC) cp_wait1(); else cp_wait0();
        __syncthreads();
        if (c + 2 < NC) { issue(c + 2, (c + 2) % 3); cp_commit(); }

        const uint32_t uAh = smb + (c % 3) * STAGE_BYTES;
        const uint32_t uAl = uAh + BUF;
        const uint32_t uBh = uAh + 2 * BUF;
#pragma unroll
        for (int ksp = 0; ksp < 2; ksp++) {
            uint32_t fAh[2][4], fAl[2][4], fBh[4][4];
#pragma unroll
            for (int mi = 0; mi < 2; mi++) {
                uint32_t off = 2u * ((wm + mi * 16 + arow) * RS + ksp * 16 + acol);
                ldmx4(fAh[mi], uAh + off);
                if (NP == 2) ldmx4(fAl[mi], uAl + off);
            }
#pragma unroll
            for (int nb = 0; nb < 4; nb++) {
                uint32_t off = 2u * ((wn + nb * 16 + bn_off) * RS + ksp * 16 + bk_off);
                ldmx4(fBh[nb], uBh + off);
            }
#pragma unroll
            for (int mi = 0; mi < 2; mi++)
#pragma unroll
                for (int nf = 0; nf < 8; nf++) {
                    const uint32_t* bh = &fBh[nf >> 1][(nf & 1) * 2];
                    mma_f16(acc[mi][nf], fAh[mi], bh[0], bh[1]);
                    if (NP == 2) mma_f16(acc[mi][nf], fAl[mi], bh[0], bh[1]);
                }
        }
    }
}

// ====== merged generator GEMM (M/V/S/Q), m-fastest raster, fp16 out ========
// z 0/1 (M/V): 1-pass (hi-only consumers); z 2/3 (S/Q): 2-pass hi+lo out.
__global__ void __launch_bounds__(256, 2) gen_gemm(
    const float* __restrict__ mb, const float* __restrict__ vb,
    const float* __restrict__ sb, const float* __restrict__ qb)
{
    extern __shared__ char sm[];

    const __half* Wh; const float* bias;
    __half *Ch, *Cl; int Nout, nt;
    switch (blockIdx.z) {
        case 0: Wh = g_mwh; bias = mb; Ch = g_Mh; Cl = nullptr; Nout = 16384; nt = 128; break;
        case 1: Wh = g_vwh; bias = vb; Ch = g_Vh; Cl = nullptr; Nout = 16384; nt = 128; break;
        case 2: Wh = g_swh; bias = sb; Ch = g_Sh; Cl = g_Sl;    Nout = 4096;  nt = 32;  break;
        default:Wh = g_qwh; bias = qb; Ch = g_Qh; Cl = g_Ql;    Nout = 4096;  nt = 32;  break;
    }
    if ((int)blockIdx.y >= nt) return;

    const int m0 = blockIdx.x * 128;
    const int n0 = blockIdx.y * 128;

    float acc[2][8][4];
    if (blockIdx.z < 2)
        gemm_core<1>(acc, g_qvh, g_qvl, Wh, sm, m0, n0, 2400, 256, 0, 8);
    else
        gemm_core<2>(acc, g_qvh, g_qvl, Wh, sm, m0, n0, 2400, 256, 0, 8);

    const int lane = threadIdx.x & 31, wid = threadIdx.x >> 5;
    const int wm = (wid & 3) * 32, wn = (wid >> 2) * 64;
    const int erow = lane >> 2, ecol = (lane & 3) * 2;
    const bool wantLo = (Cl != nullptr);
#pragma unroll
    for (int mi = 0; mi < 2; mi++) {
        int r0 = m0 + wm + mi * 16 + erow;
#pragma unroll
        for (int half = 0; half < 2; half++) {
            int r = r0 + half * 8;
            if (r >= 2400) continue;
#pragma unroll
            for (int nf = 0; nf < 8; nf++) {
                int col = n0 + wn + nf * 8 + ecol;
                float x0 = acc[mi][nf][half * 2 + 0] + __ldg(bias + col);
                float x1 = acc[mi][nf][half * 2 + 1] + __ldg(bias + col + 1);
                size_t o = (size_t)r * Nout + col;
                if (wantLo) {
                    uint32_t hp, lp;
                    split2_pack(x0, x1, hp, lp);
                    *(uint32_t*)(Ch + o) = hp;
                    *(uint32_t*)(Cl + o) = lp;
                } else {
                    *(uint32_t*)(Ch + o) = pack2h(x0, x1);
                }
            }
        }
    }
}

// ===== output-projection GEMM (uneven split-K=3, single wave, fp32 out) ====
__global__ void __launch_bounds__(256, 2) hmma_gemm(
    const __half* __restrict__ Ah0, const __half* __restrict__ Al0,
    const __half* __restrict__ Wh0,
    const float* __restrict__ b0, float* __restrict__ C0,
    const __half* __restrict__ Ah1, const __half* __restrict__ Al1,
    const __half* __restrict__ Wh1,
    const float* __restrict__ b1, float* __restrict__ C1,
    int M, int Nout, int K, int kPerCta, int splitk, size_t sliceStride)
{
    extern __shared__ char sm[];

    const int z  = blockIdx.z / splitk;
    const int ks = blockIdx.z % splitk;
    const __half* Ah = z ? Ah1 : Ah0;
    const __half* Al = z ? Al1 : Al0;
    const __half* Wh = z ? Wh1 : Wh0;
    const float* bias = z ? b1 : b0;
    float* Cp = (z ? C1 : C0) + (size_t)ks * sliceStride;

    const int m0 = blockIdx.y * 128;
    const int n0 = blockIdx.x * 128;
    const int kBegin = ks * kPerCta;
    const int kLen   = (ks == splitk - 1) ? (K - kBegin) : kPerCta;

    float acc[2][8][4];
    gemm_core<2>(acc, Ah, Al, Wh, sm, m0, n0, M, K, kBegin, kLen / 32);

    const bool addB = (ks == 0);
    const int lane = threadIdx.x & 31, wid = threadIdx.x >> 5;
    const int wm = (wid & 3) * 32, wn = (wid >> 2) * 64;
    const int erow = lane >> 2, ecol = (lane & 3) * 2;
#pragma unroll
    for (int mi = 0; mi < 2; mi++) {
        int r0 = m0 + wm + mi * 16 + erow;
#pragma unroll
        for (int half = 0; half < 2; half++) {
            int r = r0 + half * 8;
            if (r >= M) continue;
#pragma unroll
            for (int nf = 0; nf < 8; nf++) {
                int col = n0 + wn + nf * 8 + ecol;
                float x0 = acc[mi][nf][half * 2 + 0];
                float x1 = acc[mi][nf][half * 2 + 1];
                if (addB) { x0 += __ldg(bias + col); x1 += __ldg(bias + col + 1); }
                *(float2*)(Cp + (size_t)r * Nout + col) = make_float2(x0, x1);
            }
        }
    }
}

// ========= fused per-(bn,g) kernel (HMMA, mixed 2/3-pass, ~24 KB smem) =====
static constexpr int STW = 72;
static constexpr int STN = 40;

__device__ __forceinline__ void ln2048_relu(float acc[4][4], float* red) {
    float s = 0.f, q = 0.f;
#pragma unroll
    for (int i = 0; i < 4; i++)
#pragma unroll
        for (int j = 0; j < 4; j++) { s += acc[i][j]; q += acc[i][j] * acc[i][j]; }
#pragma unroll
    for (int o = 16; o > 0; o >>= 1) {
        s += __shfl_xor_sync(0xffffffffu, s, o);
        q += __shfl_xor_sync(0xffffffffu, q, o);
    }
    int w = threadIdx.x >> 5;
    __syncthreads();
    if ((threadIdx.x & 31) == 0) { red[w] = s; red[4 + w] = q; }
    __syncthreads();
    s = red[0] + red[1] + red[2] + red[3];
    q = red[4] + red[5] + red[6] + red[7];
    float mean = s * (1.f / 2048.f);
    float var  = q * (1.f / 2048.f) - mean * mean;
    float inv  = rsqrtf(var + 1e-5f);
#pragma unroll
    for (int i = 0; i < 4; i++)
#pragma unroll
        for (int j = 0; j < 4; j++)
            acc[i][j] = fmaxf((acc[i][j] - mean) * inv, 0.f);
}

struct ALoadS {
    uint32_t addrH, addrL;
    __device__ __forceinline__ void load(int kt, uint32_t aH[4], uint32_t aL[4]) const {
        ldmx4(aH, addrH + kt * 32);
        ldmx4(aL, addrL + kt * 32);
    }
};
struct ALoadGB {
    const __half *H, *L; int ld, r0, k0;
    __device__ __forceinline__ void load(int kt, uint32_t aH[4], uint32_t aL[4]) const {
        int k = kt * 16 + k0;
        aH[0] = *(const uint32_t*)(H + r0 * ld + k);
        aH[1] = *(const uint32_t*)(H + (r0 + 8) * ld + k);
        aH[2] = *(const uint32_t*)(H + r0 * ld + k + 8);
        aH[3] = *(const uint32_t*)(H + (r0 + 8) * ld + k + 8);
        aL[0] = *(const uint32_t*)(L + r0 * ld + k);
        aL[1] = *(const uint32_t*)(L + (r0 + 8) * ld + k);
        aL[2] = *(const uint32_t*)(L + r0 * ld + k + 8);
        aL[3] = *(const uint32_t*)(L + (r0 + 8) * ld + k + 8);
    }
};
struct ALoadGF {
    const float* A; int ld, r0, k0;
    __device__ __forceinline__ void load(int kt, uint32_t aH[4], uint32_t aL[4]) const {
        int k = kt * 16 + k0;
        float2 v0 = *(const float2*)(A + r0 * ld + k);
        float2 v1 = *(const float2*)(A + (r0 + 8) * ld + k);
        float2 v2 = *(const float2*)(A + r0 * ld + k + 8);
        float2 v3 = *(const float2*)(A + (r0 + 8) * ld + k + 8);
        split2_pack(v0.x, v0.y, aH[0], aL[0]);
        split2_pack(v1.x, v1.y, aH[1], aL[1]);
        split2_pack(v2.x, v2.y, aH[2], aL[2]);
        split2_pack(v3.x, v3.y, aH[3], aL[3]);
    }
};

// 2-pass: B hi only
template<class AL, int NB, int KT, bool TRANS, int SB>
__device__ __forceinline__ void mm2p(float acc[NB][4], const AL& al,
    const __half* BH, int wn, int lane)
{
    const int b1 = ((lane >> 4) << 3) + (lane & 7);
    const int b2 = ((lane >> 3) & 1) * 8;
#pragma unroll
    for (int i = 0; i < NB; i++)
#pragma unroll
        for (int j = 0; j < 4; j++) acc[i][j] = 0.f;
#pragma unroll
    for (int kt = 0; kt < KT; kt++) {
        uint32_t aH[4], aL[4];
        al.load(kt, aH, aL);
#pragma unroll
        for (int nt = 0; nt < NB / 2; nt++) {
            uint32_t bH[4];
            if (TRANS) ldmx4_t(bH, smem_u32(BH + (kt * 16 + b1) * SB + wn + nt * 16 + b2));
            else       ldmx4(bH, smem_u32(BH + (wn + nt * 16 + b1) * SB + kt * 16 + b2));
#pragma unroll
            for (int h = 0; h < 2; h++) {
                int nb = nt * 2 + h;
                uint32_t h0, h1;
                if (TRANS) { h0 = bH[h]; h1 = bH[h + 2]; }
                else       { h0 = bH[2 * h]; h1 = bH[2 * h + 1]; }
                mma_f16(acc[nb], aH, h0, h1);
                mma_f16(acc[nb], aL, h0, h1);
            }
        }
    }
}

// 3-pass: B hi+lo
template<class AL, int NB, int KT, bool TRANS, int SB>
__device__ __forceinline__ void mm3p(float acc[NB][4], const AL& al,
    const __half* BH, const __half* BL, int wn, int lane)
{
    const int b1 = ((lane >> 4) << 3) + (lane & 7);
    const int b2 = ((lane >> 3) & 1) * 8;
#pragma unroll
    for (int i = 0; i < NB; i++)
#pragma unroll
        for (int j = 0; j < 4; j++) acc[i][j] = 0.f;
#pragma unroll
    for (int kt = 0; kt < KT; kt++) {
        uint32_t aH[4], aL[4];
        al.load(kt, aH, aL);
#pragma unroll
        for (int nt = 0; nt < NB / 2; nt++) {
            uint32_t bH[4], bL[4];
            if (TRANS) {
                ldmx4_t(bH, smem_u32(BH + (kt * 16 + b1) * SB + wn + nt * 16 + b2));
                ldmx4_t(bL, smem_u32(BL + (kt * 16 + b1) * SB + wn + nt * 16 + b2));
            } else {
                ldmx4(bH, smem_u32(BH + (wn + nt * 16 + b1) * SB + kt * 16 + b2));
                ldmx4(bL, smem_u32(BL + (wn + nt * 16 + b1) * SB + kt * 16 + b2));
            }
#pragma unroll
            for (int h = 0; h < 2; h++) {
                int nb = nt * 2 + h;
                uint32_t h0, h1, l0, l1;
                if (TRANS) { h0 = bH[h]; h1 = bH[h + 2]; l0 = bL[h]; l1 = bL[h + 2]; }
                else       { h0 = bH[2 * h]; h1 = bH[2 * h + 1];
                             l0 = bL[2 * h]; l1 = bL[2 * h + 1]; }
                mma_f16(acc[nb], aH, h0, h1);
                mma_f16(acc[nb], aL, h0, h1);
                mma_f16(acc[nb], aH, l0, l1);
            }
        }
    }
}

// hi-only global -> smem copy with padded stride
template<int W, int ST>
__device__ __forceinline__ void load_h1_smem(const __half* __restrict__ srcH,
                                             int n, __half* dh, int tid)
{
#pragma unroll
    for (int idx = tid * 8; idx < n; idx += 1024) {
        int row = idx / W, col = idx % W;
        *(uint4*)(dh + row * ST + col) = *(const uint4*)(srcH + idx);
    }
}

__global__ void __launch_bounds__(128, 6) fused_bg(
    const float* __restrict__ feats,
    const float* __restrict__ kw_g, const float* __restrict__ kb_g)
{
    __shared__ __align__(16) __half wS[64 * STW];
    __shared__ __align__(16) __half xS[2 * 32 * STW];
    __shared__ __align__(16) __half sS[2 * 32 * STN];
    __shared__ float red[8];

    __half *wH = wS;
    __half *xH = xS, *xL = xS + 32 * STW;
    __half *sH = sS, *sL = sS + 32 * STN;
    float* sc = (float*)wS;   // overlays dead w region at stage 5+ (4608 B)

    const int bn = blockIdx.x, g = blockIdx.y;
    const int tid = threadIdx.x;
    const int lane = tid & 31, wrp = tid >> 5;
    const int rw   = (wrp & 1) * 16;
    const int wn32 = (wrp >> 1) * 32;
    const int wn16 = (wrp >> 1) * 16;
    const int lr = lane >> 2, lc = 2 * (lane & 3);
    const int fr0 = rw + lr, fk0 = lc;
    const size_t bg = (size_t)bn * 4 + g;

    load_h1_smem<64, STW>(g_Mh + bg * 4096, 4096, wH, tid);
    __syncthreads();

    float acc[4][4];
    const ALoadGF af{feats + bg * 2048, 64, fr0, fk0};

    // stage 1: fM = relu(ln2d(f @ M)) -> x (2-pass; x stored hi+lo)
    mm2p<ALoadGF, 4, 4, true, STW>(acc, af, wH, wn32, lane);
    ln2048_relu(acc, red);
    load_h1_smem<64, STW>(g_Vh + bg * 4096, 4096, wH, tid);   // w dead -> Vw
#pragma unroll
    for (int nb = 0; nb < 4; nb++) {
        int c = wn32 + nb * 8 + lc;
        uint32_t hp, lp;
        split2_pack(acc[nb][0], acc[nb][1], hp, lp);
        *(uint32_t*)(xH + fr0 * STW + c) = hp;
        *(uint32_t*)(xL + fr0 * STW + c) = lp;
        split2_pack(acc[nb][2], acc[nb][3], hp, lp);
        *(uint32_t*)(xH + (fr0 + 8) * STW + c) = hp;
        *(uint32_t*)(xL + (fr0 + 8) * STW + c) = lp;
    }
    __syncthreads();

    // stage 2: fMS = relu(ln2d(S @ fM)) -> global (3-pass on x)
    {
        const ALoadGB as{g_Sh + bg * 1024, g_Sl + bg * 1024, 32, fr0, fk0};
        mm3p<ALoadGB, 4, 2, true, STW>(acc, as, xH, xL, wn32, lane);
    }
    ln2048_relu(acc, red);
#pragma unroll
    for (int nb = 0; nb < 4; nb++) {
        int c = wn32 + nb * 8 + lc;
        size_t o0 = bg * 2048 + (size_t)fr0 * 64 + c;
        size_t o1 = o0 + 8 * 64;
        uint32_t hp, lp;
        split2_pack(acc[nb][0], acc[nb][1], hp, lp);
        *(uint32_t*)(g_FMSh + o0) = hp;
        *(uint32_t*)(g_FMSl + o0) = lp;
        split2_pack(acc[nb][2], acc[nb][3], hp, lp);
        *(uint32_t*)(g_FMSh + o1) = hp;
        *(uint32_t*)(g_FMSl + o1) = lp;
    }
    __syncthreads();

    // stage 3: v = relu(ln2d(f @ Vw)) -> x (2-pass)
    mm2p<ALoadGF, 4, 4, true, STW>(acc, af, wH, wn32, lane);
    ln2048_relu(acc, red);
#pragma unroll
    for (int nb = 0; nb < 4; nb++) {
        int c = wn32 + nb * 8 + lc;
        uint32_t hp, lp;
        split2_pack(acc[nb][0], acc[nb][1], hp, lp);
        *(uint32_t*)(xH + fr0 * STW + c) = hp;
        *(uint32_t*)(xL + fr0 * STW + c) = lp;
        split2_pack(acc[nb][2], acc[nb][3], hp, lp);
        *(uint32_t*)(xH + (fr0 + 8) * STW + c) = hp;
        *(uint32_t*)(xL + (fr0 + 8) * STW + c) = lp;
    }
    __syncthreads();

    float a2[2][4];

    // stage 4: k = kw @ v^T + kb -> sH (2-pass: k stored hi-only anyway)
    {
        const ALoadGF akw{kw_g + g * 2048, 64, fr0, fk0};
        mm2p<ALoadGF, 2, 4, false, STW>(a2, akw, xH, wn16, lane);
        float b0 = __ldg(kb_g + g * 32 + fr0);
        float b1 = __ldg(kb_g + g * 32 + fr0 + 8);
#pragma unroll
        for (int nb = 0; nb < 2; nb++) {
            int c = wn16 + nb * 8 + lc;
            *(uint32_t*)(sH + fr0 * STN + c)       = pack2h(a2[nb][0] + b0, a2[nb][1] + b0);
            *(uint32_t*)(sH + (fr0 + 8) * STN + c) = pack2h(a2[nb][2] + b1, a2[nb][3] + b1);
        }
    }
    __syncthreads();

    // stage 5: scores = q @ k -> sc (2-pass; k hi only)
    {
        const ALoadGB aq{g_Qh + bg * 1024, g_Ql + bg * 1024, 32, fr0, fk0};
        mm2p<ALoadGB, 2, 2, true, STN>(a2, aq, sH, wn16, lane);
#pragma unroll
        for (int nb = 0; nb < 2; nb++) {
            int c = wn16 + nb * 8 + lc;
            *(float2*)(sc + fr0 * 36 + c)       = make_float2(a2[nb][0], a2[nb][1]);
            *(float2*)(sc + (fr0 + 8) * 36 + c) = make_float2(a2[nb][2], a2[nb][3]);
        }
    }
    __syncthreads();

    // stage 6: softmax(sc / 8) -> att hi/lo in s buffers
    {
        const int tx8 = tid & 7, ty16 = tid >> 3;
#pragma unroll
        for (int i = 0; i < 2; i++) {
            int row = 2 * ty16 + i;
            float v[4];
#pragma unroll
            for (int j = 0; j < 4; j++) v[j] = sc[row * 36 + 4 * tx8 + j];
            float m = fmaxf(fmaxf(v[0], v[1]), fmaxf(v[2], v[3]));
#pragma unroll
            for (int o = 4; o > 0; o >>= 1)
                m = fmaxf(m, __shfl_xor_sync(0xffffffffu, m, o));
            float s = 0.f;
#pragma unroll
            for (int j = 0; j < 4; j++) { v[j] = __expf((v[j] - m) * 0.125f); s += v[j]; }
#pragma unroll
            for (int o = 4; o > 0; o >>= 1)
                s += __shfl_xor_sync(0xffffffffu, s, o);
            float inv = __frcp_rn(s);
#pragma unroll
            for (int j = 0; j < 4; j++) {
                float p = v[j] * inv;
                __half h, l;
                split_h(p, h, l);
                sH[row * STN + 4 * tx8 + j] = h;
                sL[row * STN + 4 * tx8 + j] = l;
            }
        }
    }
    __syncthreads();

    // stage 7: fc = relu(ln2d(att @ v)) -> global (3-pass on x)
    {
        const ALoadS aatt{
            smem_u32(sH + (rw + (lane & 15)) * STN + (lane >> 4) * 8),
            smem_u32(sL + (rw + (lane & 15)) * STN + (lane >> 4) * 8)};
        mm3p<ALoadS, 4, 2, true, STW>(acc, aatt, xH, xL, wn32, lane);
    }
    ln2048_relu(acc, red);
#pragma unroll
    for (int nb = 0; nb < 4; nb++) {
        int c = wn32 + nb * 8 + lc;
        size_t o0 = bg * 2048 + (size_t)fr0 * 64 + c;
        size_t o1 = o0 + 8 * 64;
        uint32_t hp, lp;
        split2_pack(acc[nb][0], acc[nb][1], hp, lp);
        *(uint32_t*)(g_FCh + o0) = hp;
        *(uint32_t*)(g_FCl + o0) = lp;
        split2_pack(acc[nb][2], acc[nb][3], hp, lp);
        *(uint32_t*)(g_FCh + o1) = hp;
        *(uint32_t*)(g_FCl + o1) = lp;
    }
}

// ============== residual + split-K reduce + affine LayerNorm ===============
__global__ void __launch_bounds__(256) final_ln(
    const float* __restrict__ qv,
    const float* __restrict__ wA, const float* __restrict__ bA,
    const float* __restrict__ wB, const float* __restrict__ bB,
    float* __restrict__ out)
{
    const int r = blockIdx.x, z = blockIdx.y, c = threadIdx.x;
    const float* w = z ? wB : wA;
    const float* b = z ? bB : bA;
    float x = qv[(size_t)r * 256 + c];
#pragma unroll
    for (int k = 0; k < 3; k++)
        x += g_P[(size_t)(z * 3 + k) * 614400 + (size_t)r * 256 + c];

    __shared__ float sred[16];
    float s = x, q = x * x;
#pragma unroll
    for (int o = 16; o > 0; o >>= 1) {
        s += __shfl_xor_sync(0xffffffffu, s, o);
        q += __shfl_xor_sync(0xffffffffu, q, o);
    }
    int wp = threadIdx.x >> 5;
    if ((threadIdx.x & 31) == 0) { sred[wp] = s; sred[8 + wp] = q; }
    __syncthreads();
    float S = 0.f, Q2 = 0.f;
#pragma unroll
    for (int i = 0; i < 8; i++) { S += sred[i]; Q2 += sred[8 + i]; }
    float mean = S * (1.f / 256.f);
    float var  = Q2 * (1.f / 256.f) - mean * mean;
    float inv  = rsqrtf(var + 1e-5f);
    out[(size_t)z * 614400 + (size_t)r * 256 + c] = (x - mean) * inv * w[c] + b[c];
}

// ================================ launcher =================================
extern "C" void kernel_launch(void* const* d_in, const int* in_sizes, int n_in,
                              void* d_out, int out_size)
{
    const float* feats = (const float*)d_in[0];
    const float* qv    = (const float*)d_in[1];
    const float* m_w   = (const float*)d_in[7];
    const float* m_b   = (const float*)d_in[8];
    const float* s_w   = (const float*)d_in[9];
    const float* s_b   = (const float*)d_in[10];
    const float* q_w   = (const float*)d_in[11];
    const float* q_b   = (const float*)d_in[12];
    const float* v_w   = (const float*)d_in[13];
    const float* v_b   = (const float*)d_in[14];
    const float* k_w   = (const float*)d_in[15];
    const float* k_b   = (const float*)d_in[16];
    const float* Wv_w  = (const float*)d_in[17];
    const float* Wv_b  = (const float*)d_in[18];
    const float* Wv2_w = (const float*)d_in[19];
    const float* Wv2_b = (const float*)d_in[20];
    const float* lnA_w = (const float*)d_in[21];
    const float* lnA_b = (const float*)d_in[22];
    const float* lnB_w = (const float*)d_in[23];
    const float* lnB_b = (const float*)d_in[24];
    float* out = (float*)d_out;

    float* gP;
    cudaGetSymbolAddress((void**)&gP, g_P);
    __half *Wvh, *W2h, *FMSh, *FMSl, *FCh, *FCl;
    cudaGetSymbolAddress((void**)&Wvh, g_Wvh);
    cudaGetSymbolAddress((void**)&W2h, g_W2h);
    cudaGetSymbolAddress((void**)&FMSh, g_FMSh); cudaGetSymbolAddress((void**)&FMSl, g_FMSl);
    cudaGetSymbolAddress((void**)&FCh, g_FCh);   cudaGetSymbolAddress((void**)&FCl, g_FCl);

    cudaFuncSetAttribute(gen_gemm, cudaFuncAttributeMaxDynamicSharedMemorySize, GEMM_SMEM);
    cudaFuncSetAttribute(hmma_gemm, cudaFuncAttributeMaxDynamicSharedMemorySize, GEMM_SMEM);

    // 0) split fp32 operands into fp16 (qv hi+lo, weights hi only)
    split_kernel<<<dim3(4096, 1, 7), 256>>>(qv, m_w, v_w, s_w, q_w, Wv_w, Wv2_w);

    // 1) merged M/V/S/Q generators (M/V 1-pass; S/Q 2-pass)
    gen_gemm<<<dim3(19, 128, 4), 256, GEMM_SMEM>>>(m_b, v_b, s_b, q_b);

    // 2) fused per-(bn,g) dynamic conv + attention (mixed 2/3-pass)
    fused_bg<<<dim3(2400, 4), 128>>>(feats, k_w, k_b);

    // 3) output projections: uneven split-K=3 (2720/2720/2752) -> 228 CTAs,
    //    exactly one wave at 2 CTAs/SM
    hmma_gemm<<<dim3(2, 19, 6), 256, GEMM_SMEM>>>(
        FMSh, FMSl, Wvh, Wv_b, gP,
        FCh,  FCl,  W2h, Wv2_b, gP + 3 * 614400,
        2400, 256, 8192, 2720, 3, 614400);

    // 4) residual + split-K reduce + affine LayerNorm
    final_ln<<<dim3(2400, 2), 256>>>(qv, lnA_w, lnA_b, lnB_w, lnB_b, out);
}

// round 17
// speedup vs baseline: 1.2087x; 1.2087x over previous
#include <cuda_runtime.h>
#include <cuda_fp16.h>
#include <cstdint>

// ============================ problem constants ============================
// B=8, N=300 -> BN=2400; G=4; P=O=32; CG=DG=64; IN_DIM=OUT_DIM=256; TEMPER=8

// ===================== scratch (__device__ globals) ========================
__device__ float g_P[9830400];    // split-K slices of (2400,256)

__device__ __half g_Mh[39321600];                 // hi only (B operand)
__device__ __half g_Vh[39321600];
__device__ __half g_Sh[9830400],  g_Sl[9830400];  // A operand: hi+lo
__device__ __half g_Qh[9830400],  g_Ql[9830400];

__device__ __half g_qvh[614400],  g_qvl[614400];  // A operand: hi+lo
__device__ __half g_mwh[4194304];                 // B operands: hi only
__device__ __half g_vwh[4194304];
__device__ __half g_swh[1048576];
__device__ __half g_qwh[1048576];
__device__ __half g_Wvh[2097152];
__device__ __half g_W2h[2097152];
__device__ __half g_FMSh[19660800];               // hi only (1-pass hmma A)
__device__ __half g_FCh[19660800];

// ============================ small helpers ================================
__device__ __forceinline__ uint32_t smem_u32(const void* p) {
    uint32_t a;
    asm("{ .reg .u64 t; cvta.to.shared.u64 t, %1; cvt.u32.u64 %0, t; }"
        : "=r"(a) : "l"(p));
    return a;
}
__device__ __forceinline__ void split_h(float x, __half& h, __half& l) {
    h = __float2half_rn(x);
    l = __float2half_rn(x - __half2float(h));
}
__device__ __forceinline__ void ldmx4(uint32_t r[4], uint32_t addr) {
    asm volatile("ldmatrix.sync.aligned.m8n8.x4.shared.b16 {%0,%1,%2,%3}, [%4];"
                 : "=r"(r[0]), "=r"(r[1]), "=r"(r[2]), "=r"(r[3]) : "r"(addr));
}
__device__ __forceinline__ void ldmx4_t(uint32_t r[4], uint32_t addr) {
    asm volatile("ldmatrix.sync.aligned.m8n8.x4.trans.shared.b16 {%0,%1,%2,%3}, [%4];"
                 : "=r"(r[0]), "=r"(r[1]), "=r"(r[2]), "=r"(r[3]) : "r"(addr));
}
__device__ __forceinline__ void mma_f16(float d[4], const uint32_t a[4],
                                        const uint32_t b0, const uint32_t b1) {
    asm volatile(
        "mma.sync.aligned.m16n8k16.row.col.f32.f16.f16.f32 "
        "{%0,%1,%2,%3}, {%4,%5,%6,%7}, {%8,%9}, {%0,%1,%2,%3};"
        : "+f"(d[0]), "+f"(d[1]), "+f"(d[2]), "+f"(d[3])
        : "r"(a[0]), "r"(a[1]), "r"(a[2]), "r"(a[3]), "r"(b0), "r"(b1));
}
__device__ __forceinline__ void split2_pack(float a, float b, uint32_t& hp, uint32_t& lp) {
    __half ha = __float2half_rn(a), hb = __float2half_rn(b);
    union { __half h[2]; uint32_t u; } H, L;
    H.h[0] = ha; H.h[1] = hb;
    L.h[0] = __float2half_rn(a - __half2float(ha));
    L.h[1] = __float2half_rn(b - __half2float(hb));
    hp = H.u; lp = L.u;
}
__device__ __forceinline__ uint32_t pack2h(float a, float b) {
    union { __half h[2]; uint32_t u; } U;
    U.h[0] = __float2half_rn(a); U.h[1] = __float2half_rn(b);
    return U.u;
}
// cp.async helpers
__device__ __forceinline__ void cp_async16(uint32_t saddr, const void* g) {
    asm volatile("cp.async.cg.shared.global [%0], [%1], 16;"
                 :: "r"(saddr), "l"(g));
}
__device__ __forceinline__ void cp_async16p(uint32_t saddr, const void* g, bool v) {
    int sz = v ? 16 : 0;
    asm volatile("cp.async.cg.shared.global [%0], [%1], 16, %2;"
                 :: "r"(saddr), "l"(g), "r"(sz));
}
__device__ __forceinline__ void cp_commit() {
    asm volatile("cp.async.commit_group;" ::: "memory");
}
__device__ __forceinline__ void cp_wait0() {
    asm volatile("cp.async.wait_group 0;" ::: "memory");
}
__device__ __forceinline__ void cp_wait1() {
    asm volatile("cp.async.wait_group 1;" ::: "memory");
}

// ================= operand split prep (fp32 -> fp16) =======================
// z==0 (qv): hi+lo. z>=1 (weights, B operands): hi only.
__global__ void __launch_bounds__(256) split_kernel(
    const float* __restrict__ qv, const float* __restrict__ mw,
    const float* __restrict__ vw, const float* __restrict__ sw,
    const float* __restrict__ qw, const float* __restrict__ Wv,
    const float* __restrict__ W2)
{
    const float* src; __half *dh, *dl = nullptr; int n;
    switch (blockIdx.z) {
        case 0: src = qv; dh = g_qvh; dl = g_qvl; n = 614400;  break;
        case 1: src = mw; dh = g_mwh; n = 4194304; break;
        case 2: src = vw; dh = g_vwh; n = 4194304; break;
        case 3: src = sw; dh = g_swh; n = 1048576; break;
        case 4: src = qw; dh = g_qwh; n = 1048576; break;
        case 5: src = Wv; dh = g_Wvh; n = 2097152; break;
        default:src = W2; dh = g_W2h; n = 2097152; break;
    }
    int i = (blockIdx.x * 256 + threadIdx.x) * 4;
    if (i >= n) return;
    float4 v = *(const float4*)(src + i);
    union U { __half b[4]; uint2 u; } H, L;
    split_h(v.x, H.b[0], L.b[0]);
    split_h(v.y, H.b[1], L.b[1]);
    split_h(v.z, H.b[2], L.b[2]);
    split_h(v.w, H.b[3], L.b[3]);
    *(uint2*)(dh + i) = H.u;
    if (dl) *(uint2*)(dl + i) = L.u;
}

// ====== shared GEMM core: fp16, NP passes, cp.async 3-stage pipeline =======
static constexpr int RS = 40;
static constexpr int BUF = 128 * RS * 2;
static constexpr int STAGE_BYTES = 3 * BUF;         // Ah|Al|Bh
static constexpr int GEMM_SMEM = 3 * STAGE_BYTES;   // 92160 B

template<int NP>
__device__ __forceinline__ void gemm_core(
    float acc[2][8][4],
    const __half* __restrict__ Ah, const __half* __restrict__ Al,
    const __half* __restrict__ Wh,
    char* sm, int m0, int n0, int M, int lda, int kBegin, int NC)
{
    const int tid = threadIdx.x, wid = tid >> 5, lane = tid & 31;
    const int wm = (wid & 3) * 32;
    const int wn = (wid >> 2) * 64;
    const int lrow = tid >> 2;
    const int lseg = (tid & 3) * 8;
    const uint32_t smb = smem_u32(sm);

    const int arow = lane & 15, acol = (lane >> 4) * 8;
    const int bgrp = lane >> 3, brow = lane & 7;
    const int bn_off = (bgrp >> 1) * 8 + brow;
    const int bk_off = (bgrp & 1) * 8;

#pragma unroll
    for (int i = 0; i < 2; i++)
#pragma unroll
        for (int j = 0; j < 8; j++)
#pragma unroll
            for (int q = 0; q < 4; q++) acc[i][j][q] = 0.f;

    auto issue = [&](int c, int s) {
        const int kk = kBegin + c * 32;
        const uint32_t sb = smb + s * STAGE_BYTES;
#pragma unroll
        for (int j = 0; j < 2; j++) {
            int row = lrow + 64 * j;
            int gm = m0 + row;
            bool va = (gm < M);
            int gmc = va ? gm : (M - 1);
            uint32_t off = (uint32_t)(row * RS + lseg) * 2;
            cp_async16p(sb + off, Ah + (size_t)gmc * lda + kk + lseg, va);
            if (NP == 2)
                cp_async16p(sb + BUF + off, Al + (size_t)gmc * lda + kk + lseg, va);
            cp_async16(sb + 2 * BUF + off, Wh + (size_t)(n0 + row) * lda + kk + lseg);
        }
    };

    issue(0, 0); cp_commit();
    if (NC > 1) { issue(1, 1); cp_commit(); }

    for (int c = 0; c < NC; c++) {
        if (c + 1 < NC) cp_wait1(); else cp_wait0();
        __syncthreads();
        if (c + 2 < NC) { issue(c + 2, (c + 2) % 3); cp_commit(); }

        const uint32_t uAh = smb + (c % 3) * STAGE_BYTES;
        const uint32_t uAl = uAh + BUF;
        const uint32_t uBh = uAh + 2 * BUF;
#pragma unroll
        for (int ksp = 0; ksp < 2; ksp++) {
            uint32_t fAh[2][4], fAl[2][4], fBh[4][4];
#pragma unroll
            for (int mi = 0; mi < 2; mi++) {
                uint32_t off = 2u * ((wm + mi * 16 + arow) * RS + ksp * 16 + acol);
                ldmx4(fAh[mi], uAh + off);
                if (NP == 2) ldmx4(fAl[mi], uAl + off);
            }
#pragma unroll
            for (int nb = 0; nb < 4; nb++) {
                uint32_t off = 2u * ((wn + nb * 16 + bn_off) * RS + ksp * 16 + bk_off);
                ldmx4(fBh[nb], uBh + off);
            }
#pragma unroll
            for (int mi = 0; mi < 2; mi++)
#pragma unroll
                for (int nf = 0; nf < 8; nf++) {
                    const uint32_t* bh = &fBh[nf >> 1][(nf & 1) * 2];
                    mma_f16(acc[mi][nf], fAh[mi], bh[0], bh[1]);
                    if (NP == 2) mma_f16(acc[mi][nf], fAl[mi], bh[0], bh[1]);
                }
        }
    }
}

// ====== merged generator GEMM (M/V/S/Q), m-fastest raster, fp16 out ========
// z 0/1 (M/V): 1-pass (hi-only consumers); z 2/3 (S/Q): 2-pass hi+lo out.
__global__ void __launch_bounds__(256, 2) gen_gemm(
    const float* __restrict__ mb, const float* __restrict__ vb,
    const float* __restrict__ sb, const float* __restrict__ qb)
{
    extern __shared__ char sm[];

    const __half* Wh; const float* bias;
    __half *Ch, *Cl; int Nout, nt;
    switch (blockIdx.z) {
        case 0: Wh = g_mwh; bias = mb; Ch = g_Mh; Cl = nullptr; Nout = 16384; nt = 128; break;
        case 1: Wh = g_vwh; bias = vb; Ch = g_Vh; Cl = nullptr; Nout = 16384; nt = 128; break;
        case 2: Wh = g_swh; bias = sb; Ch = g_Sh; Cl = g_Sl;    Nout = 4096;  nt = 32;  break;
        default:Wh = g_qwh; bias = qb; Ch = g_Qh; Cl = g_Ql;    Nout = 4096;  nt = 32;  break;
    }
    if ((int)blockIdx.y >= nt) return;

    const int m0 = blockIdx.x * 128;
    const int n0 = blockIdx.y * 128;

    float acc[2][8][4];
    if (blockIdx.z < 2)
        gemm_core<1>(acc, g_qvh, g_qvl, Wh, sm, m0, n0, 2400, 256, 0, 8);
    else
        gemm_core<2>(acc, g_qvh, g_qvl, Wh, sm, m0, n0, 2400, 256, 0, 8);

    const int lane = threadIdx.x & 31, wid = threadIdx.x >> 5;
    const int wm = (wid & 3) * 32, wn = (wid >> 2) * 64;
    const int erow = lane >> 2, ecol = (lane & 3) * 2;
    const bool wantLo = (Cl != nullptr);
#pragma unroll
    for (int mi = 0; mi < 2; mi++) {
        int r0 = m0 + wm + mi * 16 + erow;
#pragma unroll
        for (int half = 0; half < 2; half++) {
            int r = r0 + half * 8;
            if (r >= 2400) continue;
#pragma unroll
            for (int nf = 0; nf < 8; nf++) {
                int col = n0 + wn + nf * 8 + ecol;
                float x0 = acc[mi][nf][half * 2 + 0] + __ldg(bias + col);
                float x1 = acc[mi][nf][half * 2 + 1] + __ldg(bias + col + 1);
                size_t o = (size_t)r * Nout + col;
                if (wantLo) {
                    uint32_t hp, lp;
                    split2_pack(x0, x1, hp, lp);
                    *(uint32_t*)(Ch + o) = hp;
                    *(uint32_t*)(Cl + o) = lp;
                } else {
                    *(uint32_t*)(Ch + o) = pack2h(x0, x1);
                }
            }
        }
    }
}

// ===== output-projection GEMM (split-K=4, 1-pass fp16 A, fp32 out) =========
__global__ void __launch_bounds__(256, 2) hmma_gemm(
    const __half* __restrict__ Ah0, const __half* __restrict__ Wh0,
    const float* __restrict__ b0, float* __restrict__ C0,
    const __half* __restrict__ Ah1, const __half* __restrict__ Wh1,
    const float* __restrict__ b1, float* __restrict__ C1,
    int M, int Nout, int K, int kPerCta, int splitk, size_t sliceStride)
{
    extern __shared__ char sm[];

    const int z  = blockIdx.z / splitk;
    const int ks = blockIdx.z % splitk;
    const __half* Ah = z ? Ah1 : Ah0;
    const __half* Wh = z ? Wh1 : Wh0;
    const float* bias = z ? b1 : b0;
    float* Cp = (z ? C1 : C0) + (size_t)ks * sliceStride;

    const int m0 = blockIdx.y * 128;
    const int n0 = blockIdx.x * 128;
    const int kBegin = ks * kPerCta;
    const int kLen   = (ks == splitk - 1) ? (K - kBegin) : kPerCta;

    float acc[2][8][4];
    gemm_core<1>(acc, Ah, nullptr, Wh, sm, m0, n0, M, K, kBegin, kLen / 32);

    const bool addB = (ks == 0);
    const int lane = threadIdx.x & 31, wid = threadIdx.x >> 5;
    const int wm = (wid & 3) * 32, wn = (wid >> 2) * 64;
    const int erow = lane >> 2, ecol = (lane & 3) * 2;
#pragma unroll
    for (int mi = 0; mi < 2; mi++) {
        int r0 = m0 + wm + mi * 16 + erow;
#pragma unroll
        for (int half = 0; half < 2; half++) {
            int r = r0 + half * 8;
            if (r >= M) continue;
#pragma unroll
            for (int nf = 0; nf < 8; nf++) {
                int col = n0 + wn + nf * 8 + ecol;
                float x0 = acc[mi][nf][half * 2 + 0];
                float x1 = acc[mi][nf][half * 2 + 1];
                if (addB) { x0 += __ldg(bias + col); x1 += __ldg(bias + col + 1); }
                *(float2*)(Cp + (size_t)r * Nout + col) = make_float2(x0, x1);
            }
        }
    }
}

// ========= fused per-(bn,g) kernel (HMMA, mixed 2/3-pass, ~24 KB smem) =====
static constexpr int STW = 72;
static constexpr int STN = 40;

__device__ __forceinline__ void ln2048_relu(float acc[4][4], float* red) {
    float s = 0.f, q = 0.f;
#pragma unroll
    for (int i = 0; i < 4; i++)
#pragma unroll
        for (int j = 0; j < 4; j++) { s += acc[i][j]; q += acc[i][j] * acc[i][j]; }
#pragma unroll
    for (int o = 16; o > 0; o >>= 1) {
        s += __shfl_xor_sync(0xffffffffu, s, o);
        q += __shfl_xor_sync(0xffffffffu, q, o);
    }
    int w = threadIdx.x >> 5;
    __syncthreads();
    if ((threadIdx.x & 31) == 0) { red[w] = s; red[4 + w] = q; }
    __syncthreads();
    s = red[0] + red[1] + red[2] + red[3];
    q = red[4] + red[5] + red[6] + red[7];
    float mean = s * (1.f / 2048.f);
    float var  = q * (1.f / 2048.f) - mean * mean;
    float inv  = rsqrtf(var + 1e-5f);
#pragma unroll
    for (int i = 0; i < 4; i++)
#pragma unroll
        for (int j = 0; j < 4; j++)
            acc[i][j] = fmaxf((acc[i][j] - mean) * inv, 0.f);
}

struct ALoadS {
    uint32_t addrH, addrL;
    __device__ __forceinline__ void load(int kt, uint32_t aH[4], uint32_t aL[4]) const {
        ldmx4(aH, addrH + kt * 32);
        ldmx4(aL, addrL + kt * 32);
    }
};
struct ALoadGB {
    const __half *H, *L; int ld, r0, k0;
    __device__ __forceinline__ void load(int kt, uint32_t aH[4], uint32_t aL[4]) const {
        int k = kt * 16 + k0;
        aH[0] = *(const uint32_t*)(H + r0 * ld + k);
        aH[1] = *(const uint32_t*)(H + (r0 + 8) * ld + k);
        aH[2] = *(const uint32_t*)(H + r0 * ld + k + 8);
        aH[3] = *(const uint32_t*)(H + (r0 + 8) * ld + k + 8);
        aL[0] = *(const uint32_t*)(L + r0 * ld + k);
        aL[1] = *(const uint32_t*)(L + (r0 + 8) * ld + k);
        aL[2] = *(const uint32_t*)(L + r0 * ld + k + 8);
        aL[3] = *(const uint32_t*)(L + (r0 + 8) * ld + k + 8);
    }
};
struct ALoadGF {
    const float* A; int ld, r0, k0;
    __device__ __forceinline__ void load(int kt, uint32_t aH[4], uint32_t aL[4]) const {
        int k = kt * 16 + k0;
        float2 v0 = *(const float2*)(A + r0 * ld + k);
        float2 v1 = *(const float2*)(A + (r0 + 8) * ld + k);
        float2 v2 = *(const float2*)(A + r0 * ld + k + 8);
        float2 v3 = *(const float2*)(A + (r0 + 8) * ld + k + 8);
        split2_pack(v0.x, v0.y, aH[0], aL[0]);
        split2_pack(v1.x, v1.y, aH[1], aL[1]);
        split2_pack(v2.x, v2.y, aH[2], aL[2]);
        split2_pack(v3.x, v3.y, aH[3], aL[3]);
    }
};

// 2-pass: B hi only
template<class AL, int NB, int KT, bool TRANS, int SB>
__device__ __forceinline__ void mm2p(float acc[NB][4], const AL& al,
    const __half* BH, int wn, int lane)
{
    const int b1 = ((lane >> 4) << 3) + (lane & 7);
    const int b2 = ((lane >> 3) & 1) * 8;
#pragma unroll
    for (int i = 0; i < NB; i++)
#pragma unroll
        for (int j = 0; j < 4; j++) acc[i][j] = 0.f;
#pragma unroll
    for (int kt = 0; kt < KT; kt++) {
        uint32_t aH[4], aL[4];
        al.load(kt, aH, aL);
#pragma unroll
        for (int nt = 0; nt < NB / 2; nt++) {
            uint32_t bH[4];
            if (TRANS) ldmx4_t(bH, smem_u32(BH + (kt * 16 + b1) * SB + wn + nt * 16 + b2));
            else       ldmx4(bH, smem_u32(BH + (wn + nt * 16 + b1) * SB + kt * 16 + b2));
#pragma unroll
            for (int h = 0; h < 2; h++) {
                int nb = nt * 2 + h;
                uint32_t h0, h1;
                if (TRANS) { h0 = bH[h]; h1 = bH[h + 2]; }
                else       { h0 = bH[2 * h]; h1 = bH[2 * h + 1]; }
                mma_f16(acc[nb], aH, h0, h1);
                mma_f16(acc[nb], aL, h0, h1);
            }
        }
    }
}

// 3-pass: B hi+lo
template<class AL, int NB, int KT, bool TRANS, int SB>
__device__ __forceinline__ void mm3p(float acc[NB][4], const AL& al,
    const __half* BH, const __half* BL, int wn, int lane)
{
    const int b1 = ((lane >> 4) << 3) + (lane & 7);
    const int b2 = ((lane >> 3) & 1) * 8;
#pragma unroll
    for (int i = 0; i < NB; i++)
#pragma unroll
        for (int j = 0; j < 4; j++) acc[i][j] = 0.f;
#pragma unroll
    for (int kt = 0; kt < KT; kt++) {
        uint32_t aH[4], aL[4];
        al.load(kt, aH, aL);
#pragma unroll
        for (int nt = 0; nt < NB / 2; nt++) {
            uint32_t bH[4], bL[4];
            if (TRANS) {
                ldmx4_t(bH, smem_u32(BH + (kt * 16 + b1) * SB + wn + nt * 16 + b2));
                ldmx4_t(bL, smem_u32(BL + (kt * 16 + b1) * SB + wn + nt * 16 + b2));
            } else {
                ldmx4(bH, smem_u32(BH + (wn + nt * 16 + b1) * SB + kt * 16 + b2));
                ldmx4(bL, smem_u32(BL + (wn + nt * 16 + b1) * SB + kt * 16 + b2));
            }
#pragma unroll
            for (int h = 0; h < 2; h++) {
                int nb = nt * 2 + h;
                uint32_t h0, h1, l0, l1;
                if (TRANS) { h0 = bH[h]; h1 = bH[h + 2]; l0 = bL[h]; l1 = bL[h + 2]; }
                else       { h0 = bH[2 * h]; h1 = bH[2 * h + 1];
                             l0 = bL[2 * h]; l1 = bL[2 * h + 1]; }
                mma_f16(acc[nb], aH, h0, h1);
                mma_f16(acc[nb], aL, h0, h1);
                mma_f16(acc[nb], aH, l0, l1);
            }
        }
    }
}

// hi-only global -> smem copy with padded stride
template<int W, int ST>
__device__ __forceinline__ void load_h1_smem(const __half* __restrict__ srcH,
                                             int n, __half* dh, int tid)
{
#pragma unroll
    for (int idx = tid * 8; idx < n; idx += 1024) {
        int row = idx / W, col = idx % W;
        *(uint4*)(dh + row * ST + col) = *(const uint4*)(srcH + idx);
    }
}

__global__ void __launch_bounds__(128, 6) fused_bg(
    const float* __restrict__ feats,
    const float* __restrict__ kw_g, const float* __restrict__ kb_g)
{
    __shared__ __align__(16) __half wS[64 * STW];
    __shared__ __align__(16) __half xS[2 * 32 * STW];
    __shared__ __align__(16) __half sS[2 * 32 * STN];
    __shared__ float red[8];

    __half *wH = wS;
    __half *xH = xS, *xL = xS + 32 * STW;
    __half *sH = sS, *sL = sS + 32 * STN;
    float* sc = (float*)wS;   // overlays dead w region at stage 5+ (4608 B)

    const int bn = blockIdx.x, g = blockIdx.y;
    const int tid = threadIdx.x;
    const int lane = tid & 31, wrp = tid >> 5;
    const int rw   = (wrp & 1) * 16;
    const int wn32 = (wrp >> 1) * 32;
    const int wn16 = (wrp >> 1) * 16;
    const int lr = lane >> 2, lc = 2 * (lane & 3);
    const int fr0 = rw + lr, fk0 = lc;
    const size_t bg = (size_t)bn * 4 + g;

    load_h1_smem<64, STW>(g_Mh + bg * 4096, 4096, wH, tid);
    __syncthreads();

    float acc[4][4];
    const ALoadGF af{feats + bg * 2048, 64, fr0, fk0};

    // stage 1: fM = relu(ln2d(f @ M)) -> x (2-pass; x stored hi+lo)
    mm2p<ALoadGF, 4, 4, true, STW>(acc, af, wH, wn32, lane);
    ln2048_relu(acc, red);
    load_h1_smem<64, STW>(g_Vh + bg * 4096, 4096, wH, tid);   // w dead -> Vw
#pragma unroll
    for (int nb = 0; nb < 4; nb++) {
        int c = wn32 + nb * 8 + lc;
        uint32_t hp, lp;
        split2_pack(acc[nb][0], acc[nb][1], hp, lp);
        *(uint32_t*)(xH + fr0 * STW + c) = hp;
        *(uint32_t*)(xL + fr0 * STW + c) = lp;
        split2_pack(acc[nb][2], acc[nb][3], hp, lp);
        *(uint32_t*)(xH + (fr0 + 8) * STW + c) = hp;
        *(uint32_t*)(xL + (fr0 + 8) * STW + c) = lp;
    }
    __syncthreads();

    // stage 2: fMS = relu(ln2d(S @ fM)) -> global hi only (3-pass on x)
    {
        const ALoadGB as{g_Sh + bg * 1024, g_Sl + bg * 1024, 32, fr0, fk0};
        mm3p<ALoadGB, 4, 2, true, STW>(acc, as, xH, xL, wn32, lane);
    }
    ln2048_relu(acc, red);
#pragma unroll
    for (int nb = 0; nb < 4; nb++) {
        int c = wn32 + nb * 8 + lc;
        size_t o0 = bg * 2048 + (size_t)fr0 * 64 + c;
        size_t o1 = o0 + 8 * 64;
        *(uint32_t*)(g_FMSh + o0) = pack2h(acc[nb][0], acc[nb][1]);
        *(uint32_t*)(g_FMSh + o1) = pack2h(acc[nb][2], acc[nb][3]);
    }
    __syncthreads();

    // stage 3: v = relu(ln2d(f @ Vw)) -> x (2-pass)
    mm2p<ALoadGF, 4, 4, true, STW>(acc, af, wH, wn32, lane);
    ln2048_relu(acc, red);
#pragma unroll
    for (int nb = 0; nb < 4; nb++) {
        int c = wn32 + nb * 8 + lc;
        uint32_t hp, lp;
        split2_pack(acc[nb][0], acc[nb][1], hp, lp);
        *(uint32_t*)(xH + fr0 * STW + c) = hp;
        *(uint32_t*)(xL + fr0 * STW + c) = lp;
        split2_pack(acc[nb][2], acc[nb][3], hp, lp);
        *(uint32_t*)(xH + (fr0 + 8) * STW + c) = hp;
        *(uint32_t*)(xL + (fr0 + 8) * STW + c) = lp;
    }
    __syncthreads();

    float a2[2][4];

    // stage 4: k = kw @ v^T + kb -> sH (2-pass: k stored hi-only anyway)
    {
        const ALoadGF akw{kw_g + g * 2048, 64, fr0, fk0};
        mm2p<ALoadGF, 2, 4, false, STW>(a2, akw, xH, wn16, lane);
        float b0 = __ldg(kb_g + g * 32 + fr0);
        float b1 = __ldg(kb_g + g * 32 + fr0 + 8);
#pragma unroll
        for (int nb = 0; nb < 2; nb++) {
            int c = wn16 + nb * 8 + lc;
            *(uint32_t*)(sH + fr0 * STN + c)       = pack2h(a2[nb][0] + b0, a2[nb][1] + b0);
            *(uint32_t*)(sH + (fr0 + 8) * STN + c) = pack2h(a2[nb][2] + b1, a2[nb][3] + b1);
        }
    }
    __syncthreads();

    // stage 5: scores = q @ k -> sc (2-pass; k hi only)
    {
        const ALoadGB aq{g_Qh + bg * 1024, g_Ql + bg * 1024, 32, fr0, fk0};
        mm2p<ALoadGB, 2, 2, true, STN>(a2, aq, sH, wn16, lane);
#pragma unroll
        for (int nb = 0; nb < 2; nb++) {
            int c = wn16 + nb * 8 + lc;
            *(float2*)(sc + fr0 * 36 + c)       = make_float2(a2[nb][0], a2[nb][1]);
            *(float2*)(sc + (fr0 + 8) * 36 + c) = make_float2(a2[nb][2], a2[nb][3]);
        }
    }
    __syncthreads();

    // stage 6: softmax(sc / 8) -> att hi/lo in s buffers
    {
        const int tx8 = tid & 7, ty16 = tid >> 3;
#pragma unroll
        for (int i = 0; i < 2; i++) {
            int row = 2 * ty16 + i;
            float v[4];
#pragma unroll
            for (int j = 0; j < 4; j++) v[j] = sc[row * 36 + 4 * tx8 + j];
            float m = fmaxf(fmaxf(v[0], v[1]), fmaxf(v[2], v[3]));
#pragma unroll
            for (int o = 4; o > 0; o >>= 1)
                m = fmaxf(m, __shfl_xor_sync(0xffffffffu, m, o));
            float s = 0.f;
#pragma unroll
            for (int j = 0; j < 4; j++) { v[j] = __expf((v[j] - m) * 0.125f); s += v[j]; }
#pragma unroll
            for (int o = 4; o > 0; o >>= 1)
                s += __shfl_xor_sync(0xffffffffu, s, o);
            float inv = __frcp_rn(s);
#pragma unroll
            for (int j = 0; j < 4; j++) {
                float p = v[j] * inv;
                __half h, l;
                split_h(p, h, l);
                sH[row * STN + 4 * tx8 + j] = h;
                sL[row * STN + 4 * tx8 + j] = l;
            }
        }
    }
    __syncthreads();

    // stage 7: fc = relu(ln2d(att @ v)) -> global hi only (3-pass on x)
    {
        const ALoadS aatt{
            smem_u32(sH + (rw + (lane & 15)) * STN + (lane >> 4) * 8),
            smem_u32(sL + (rw + (lane & 15)) * STN + (lane >> 4) * 8)};
        mm3p<ALoadS, 4, 2, true, STW>(acc, aatt, xH, xL, wn32, lane);
    }
    ln2048_relu(acc, red);
#pragma unroll
    for (int nb = 0; nb < 4; nb++) {
        int c = wn32 + nb * 8 + lc;
        size_t o0 = bg * 2048 + (size_t)fr0 * 64 + c;
        size_t o1 = o0 + 8 * 64;
        *(uint32_t*)(g_FCh + o0) = pack2h(acc[nb][0], acc[nb][1]);
        *(uint32_t*)(g_FCh + o1) = pack2h(acc[nb][2], acc[nb][3]);
    }
}

// ============== residual + split-K reduce + affine LayerNorm ===============
__global__ void __launch_bounds__(256) final_ln(
    const float* __restrict__ qv,
    const float* __restrict__ wA, const float* __restrict__ bA,
    const float* __restrict__ wB, const float* __restrict__ bB,
    float* __restrict__ out)
{
    const int r = blockIdx.x, z = blockIdx.y, c = threadIdx.x;
    const float* w = z ? wB : wA;
    const float* b = z ? bB : bA;
    float x = qv[(size_t)r * 256 + c];
#pragma unroll
    for (int k = 0; k < 4; k++)
        x += g_P[(size_t)(z * 4 + k) * 614400 + (size_t)r * 256 + c];

    __shared__ float sred[16];
    float s = x, q = x * x;
#pragma unroll
    for (int o = 16; o > 0; o >>= 1) {
        s += __shfl_xor_sync(0xffffffffu, s, o);
        q += __shfl_xor_sync(0xffffffffu, q, o);
    }
    int wp = threadIdx.x >> 5;
    if ((threadIdx.x & 31) == 0) { sred[wp] = s; sred[8 + wp] = q; }
    __syncthreads();
    float S = 0.f, Q2 = 0.f;
#pragma unroll
    for (int i = 0; i < 8; i++) { S += sred[i]; Q2 += sred[8 + i]; }
    float mean = S * (1.f / 256.f);
    float var  = Q2 * (1.f / 256.f) - mean * mean;
    float inv  = rsqrtf(var + 1e-5f);
    out[(size_t)z * 614400 + (size_t)r * 256 + c] = (x - mean) * inv * w[c] + b[c];
}

// ================================ launcher =================================
extern "C" void kernel_launch(void* const* d_in, const int* in_sizes, int n_in,
                              void* d_out, int out_size)
{
    const float* feats = (const float*)d_in[0];
    const float* qv    = (const float*)d_in[1];
    const float* m_w   = (const float*)d_in[7];
    const float* m_b   = (const float*)d_in[8];
    const float* s_w   = (const float*)d_in[9];
    const float* s_b   = (const float*)d_in[10];
    const float* q_w   = (const float*)d_in[11];
    const float* q_b   = (const float*)d_in[12];
    const float* v_w   = (const float*)d_in[13];
    const float* v_b   = (const float*)d_in[14];
    const float* k_w   = (const float*)d_in[15];
    const float* k_b   = (const float*)d_in[16];
    const float* Wv_w  = (const float*)d_in[17];
    const float* Wv_b  = (const float*)d_in[18];
    const float* Wv2_w = (const float*)d_in[19];
    const float* Wv2_b = (const float*)d_in[20];
    const float* lnA_w = (const float*)d_in[21];
    const float* lnA_b = (const float*)d_in[22];
    const float* lnB_w = (const float*)d_in[23];
    const float* lnB_b = (const float*)d_in[24];
    float* out = (float*)d_out;

    float* gP;
    cudaGetSymbolAddress((void**)&gP, g_P);
    __half *Wvh, *W2h, *FMSh, *FCh;
    cudaGetSymbolAddress((void**)&Wvh, g_Wvh);
    cudaGetSymbolAddress((void**)&W2h, g_W2h);
    cudaGetSymbolAddress((void**)&FMSh, g_FMSh);
    cudaGetSymbolAddress((void**)&FCh, g_FCh);

    cudaFuncSetAttribute(gen_gemm, cudaFuncAttributeMaxDynamicSharedMemorySize, GEMM_SMEM);
    cudaFuncSetAttribute(hmma_gemm, cudaFuncAttributeMaxDynamicSharedMemorySize, GEMM_SMEM);

    // 0) split fp32 operands into fp16 (qv hi+lo, weights hi only)
    split_kernel<<<dim3(4096, 1, 7), 256>>>(qv, m_w, v_w, s_w, q_w, Wv_w, Wv2_w);

    // 1) merged M/V/S/Q generators (M/V 1-pass; S/Q 2-pass)
    gen_gemm<<<dim3(19, 128, 4), 256, GEMM_SMEM>>>(m_b, v_b, s_b, q_b);

    // 2) fused per-(bn,g) dynamic conv + attention (mixed 2/3-pass)
    fused_bg<<<dim3(2400, 4), 128>>>(feats, k_w, k_b);

    // 3) output projections: split-K=4 (reverted), 1-pass fp16 A
    hmma_gemm<<<dim3(2, 19, 8), 256, GEMM_SMEM>>>(
        FMSh, Wvh, Wv_b, gP,
        FCh,  W2h, Wv2_b, gP + 4 * 614400,
        2400, 256, 8192, 2048, 4, 614400);

    // 4) residual + split-K reduce + affine LayerNorm
    final_ln<<<dim3(2400, 2), 256>>>(qv, lnA_w, lnA_b, lnB_w, lnB_b, out);
}